// round 2
// baseline (speedup 1.0000x reference)
#include <cuda_runtime.h>
#include <cstddef>

// Problem constants (fixed by reference): B=16, H=8, L=512, D=64
#define BH   128
#define LEN  512
#define DIM  64
#define TI   64          // i-rows per CTA
#define NT   256         // threads per CTA
#define NJT  8           // 512/64 j-tiles

// SMEM layout (floats)
#define PQ   68          // pitch for Q/K/V tiles (16B aligned, avoids bad banks)
#define PE   516         // pitch for E rows (16B aligned)
#define OFF_Q 0
#define OFF_K (64*PQ)            // 4352
#define OFF_V (2*64*PQ)          // 8704
#define OFF_E (3*64*PQ)          // 13056
#define OFF_M (OFF_E + 64*PE)    // 46080
#define OFF_R (OFF_M + 512)      // 46592
#define SMEM_FLOATS (OFF_R + 64) // 46656 floats = 186624 bytes
#define SMEM_BYTES  (SMEM_FLOATS * 4)

__global__ void __launch_bounds__(NT, 1)
attn_fused_kernel(const float* __restrict__ q,
                  const float* __restrict__ k,
                  const float* __restrict__ v,
                  const float* __restrict__ mask,
                  float* __restrict__ out_o,     // [BH, L, D] or null
                  float* __restrict__ out_attn)  // [BH, L, L] or null
{
    extern __shared__ float sm[];
    float* Qs = sm + OFF_Q;   // transposed: Qs[d*PQ + i]
    float* Ks = sm + OFF_K;   // transposed: Ks[d*PQ + j]
    float* Vs = sm + OFF_V;   // natural:    Vs[k*PQ + d]
    float* Es = sm + OFF_E;   // Es[i*PE + j], unnormalized exp scores
    float* mc = sm + OFF_M;   // column mask term (512): 0 or 1e9
    float* rs = sm + OFF_R;   // row sums (64)

    const int bh   = blockIdx.y;
    const int i0   = blockIdx.x * TI;
    const int b    = bh >> 3;          // H = 8
    const int tid  = threadIdx.x;
    const int lane = tid & 31;
    const int w    = tid >> 5;         // warp id 0..7
    const int tx   = tid & 15;         // j/d micro-tile coord
    const int ty   = tid >> 4;         // i micro-tile coord

    // column mask: m[j] = (mask==-10000) ? 1e9 : mask
    for (int j = tid; j < LEN; j += NT) {
        float mv = mask[b * LEN + j];
        mc[j] = (mv == -10000.0f) ? 1e9f : mv;
    }

    // Load Q tile transposed: Qs[d][i].
    const float* qb = q + ((size_t)bh * LEN + i0) * DIM;
    #pragma unroll
    for (int rr = 0; rr < 8; rr++) {
        int row = rr * 8 + w;
        float q0 = qb[row * DIM + lane];
        float q1 = qb[row * DIM + lane + 32];
        Qs[lane * PQ + row]        = q0;
        Qs[(lane + 32) * PQ + row] = q1;
    }

    float oacc[4][4];
    #pragma unroll
    for (int r = 0; r < 4; r++)
        #pragma unroll
        for (int c = 0; c < 4; c++) oacc[r][c] = 0.0f;
    float rsum[4] = {0.f, 0.f, 0.f, 0.f};

    const float* kb = k + (size_t)bh * LEN * DIM;
    const float* vb = v + (size_t)bh * LEN * DIM;

    for (int jt = 0; jt < NJT; jt++) {
        const int j0 = jt * 64;
        __syncthreads();   // previous tile's consumers done before overwrite

        // K tile transposed, V tile natural; gmem reads coalesced 128B/warp
        #pragma unroll
        for (int rr = 0; rr < 8; rr++) {
            int row = rr * 8 + w;
            const float* krow = kb + (size_t)(j0 + row) * DIM;
            const float* vrow = vb + (size_t)(j0 + row) * DIM;
            float k0 = krow[lane], k1 = krow[lane + 32];
            float v0 = vrow[lane], v1 = vrow[lane + 32];
            Ks[lane * PQ + row]        = k0;
            Ks[(lane + 32) * PQ + row] = k1;
            Vs[row * PQ + lane]        = v0;
            Vs[row * PQ + lane + 32]   = v1;
        }
        __syncthreads();

        // GEMM1: S[i][j] = sum_d Q[i][d] * K[j][d]
        float acc[4][4];
        #pragma unroll
        for (int r = 0; r < 4; r++)
            #pragma unroll
            for (int c = 0; c < 4; c++) acc[r][c] = 0.0f;

        #pragma unroll 16
        for (int kk = 0; kk < DIM; kk++) {
            float qv[4];
            #pragma unroll
            for (int r = 0; r < 4; r++) qv[r] = Qs[kk * PQ + 4 * ty + r];
            float4 kv = *(const float4*)&Ks[kk * PQ + 4 * tx];
            #pragma unroll
            for (int r = 0; r < 4; r++) {
                acc[r][0] = fmaf(qv[r], kv.x, acc[r][0]);
                acc[r][1] = fmaf(qv[r], kv.y, acc[r][1]);
                acc[r][2] = fmaf(qv[r], kv.z, acc[r][2]);
                acc[r][3] = fmaf(qv[r], kv.w, acc[r][3]);
            }
        }

        // exp + masked-row fp32-collapse semantics:
        //   unmasked row i (m_i == 0): E_ij = exp(s/8 - m_j)
        //   masked row i   (m_i == 1e9): in the fp32 reference, s/8 - 1e9
        //     rounds to exactly -1e9 (ulp(1e9)=64), so after jax's max-
        //     subtraction softmax every unmasked column gets exp(0)=1 and
        //     every masked column gets exp(-1e9)=0 -> uniform distribution.
        float m0 = mc[j0 + 4 * tx + 0];
        float m1 = mc[j0 + 4 * tx + 1];
        float m2 = mc[j0 + 4 * tx + 2];
        float m3 = mc[j0 + 4 * tx + 3];
        float u0 = (m0 == 0.0f) ? 1.0f : 0.0f;
        float u1 = (m1 == 0.0f) ? 1.0f : 0.0f;
        float u2 = (m2 == 0.0f) ? 1.0f : 0.0f;
        float u3 = (m3 == 0.0f) ? 1.0f : 0.0f;
        #pragma unroll
        for (int r = 0; r < 4; r++) {
            bool rowMasked = (mc[i0 + 4 * ty + r] != 0.0f);
            float4 e4;
            e4.x = rowMasked ? u0 : __expf(fmaf(acc[r][0], 0.125f, -m0));
            e4.y = rowMasked ? u1 : __expf(fmaf(acc[r][1], 0.125f, -m1));
            e4.z = rowMasked ? u2 : __expf(fmaf(acc[r][2], 0.125f, -m2));
            e4.w = rowMasked ? u3 : __expf(fmaf(acc[r][3], 0.125f, -m3));
            rsum[r] += (e4.x + e4.y) + (e4.z + e4.w);
            *(float4*)&Es[(4 * ty + r) * PE + j0 + 4 * tx] = e4;
        }
        __syncthreads();

        // GEMM2: O[i][d] += E[i][k] * V[k][d] over this tile's 64 k's
        #pragma unroll 16
        for (int kk = 0; kk < 64; kk++) {
            float ev[4];
            #pragma unroll
            for (int r = 0; r < 4; r++) ev[r] = Es[(4 * ty + r) * PE + j0 + kk];
            float4 vv = *(const float4*)&Vs[kk * PQ + 4 * tx];
            #pragma unroll
            for (int r = 0; r < 4; r++) {
                oacc[r][0] = fmaf(ev[r], vv.x, oacc[r][0]);
                oacc[r][1] = fmaf(ev[r], vv.y, oacc[r][1]);
                oacc[r][2] = fmaf(ev[r], vv.z, oacc[r][2]);
                oacc[r][3] = fmaf(ev[r], vv.w, oacc[r][3]);
            }
        }
    }

    // reduce row sums across the 16 tx lanes (tx = lane & 15)
    #pragma unroll
    for (int r = 0; r < 4; r++) {
        float s = rsum[r];
        s += __shfl_xor_sync(0xffffffffu, s, 1);
        s += __shfl_xor_sync(0xffffffffu, s, 2);
        s += __shfl_xor_sync(0xffffffffu, s, 4);
        s += __shfl_xor_sync(0xffffffffu, s, 8);
        rsum[r] = s;
    }
    if (tx == 0) {
        #pragma unroll
        for (int r = 0; r < 4; r++) rs[4 * ty + r] = rsum[r];
    }
    __syncthreads();

    // write O = (E @ V) / rowsum
    if (out_o) {
        float* ob = out_o + ((size_t)bh * LEN + i0) * DIM;
        #pragma unroll
        for (int r = 0; r < 4; r++) {
            float inv = 1.0f / rsum[r];
            float4 o4;
            o4.x = oacc[r][0] * inv;
            o4.y = oacc[r][1] * inv;
            o4.z = oacc[r][2] * inv;
            o4.w = oacc[r][3] * inv;
            *(float4*)&ob[(4 * ty + r) * DIM + 4 * tx] = o4;
        }
    }

    // write attn = E / rowsum (normalized probabilities)
    if (out_attn) {
        float* ab = out_attn + ((size_t)bh * LEN + i0) * LEN;
        for (int idx = tid * 4; idx < TI * LEN; idx += NT * 4) {
            int row = idx >> 9;       // / 512
            int col = idx & 511;
            float inv = 1.0f / rs[row];
            float4 e4 = *(const float4*)&Es[row * PE + col];
            e4.x *= inv; e4.y *= inv; e4.z *= inv; e4.w *= inv;
            *(float4*)&ab[(size_t)row * LEN + col] = e4;
        }
    }
}

extern "C" void kernel_launch(void* const* d_in, const int* in_sizes, int n_in,
                              void* d_out, int out_size)
{
    const float* q    = (const float*)d_in[0];
    const float* k    = (const float*)d_in[1];
    const float* v    = (const float*)d_in[2];
    const float* mask = (const float*)d_in[3];

    const long long O_ELEMS = (long long)BH * LEN * DIM;   // 4194304
    const long long A_ELEMS = (long long)BH * LEN * LEN;   // 33554432

    float* out = (float*)d_out;
    float* o_ptr = nullptr;
    float* a_ptr = nullptr;
    if ((long long)out_size >= O_ELEMS + A_ELEMS) {
        o_ptr = out;
        a_ptr = out + O_ELEMS;
    } else if ((long long)out_size == A_ELEMS) {
        a_ptr = out;
    } else {
        o_ptr = out;
    }

    cudaFuncSetAttribute(attn_fused_kernel,
                         cudaFuncAttributeMaxDynamicSharedMemorySize, SMEM_BYTES);

    dim3 grid(LEN / TI, BH);   // (8, 128)
    attn_fused_kernel<<<grid, NT, SMEM_BYTES>>>(q, k, v, mask, o_ptr, a_ptr);
}

// round 3
// speedup vs baseline: 1.6256x; 1.6256x over previous
#include <cuda_runtime.h>
#include <cuda_bf16.h>
#include <cstdint>
#include <cstddef>

// Problem constants: B=16, H=8, L=512, D=64
#define BH   128
#define LEN  512
#define DIM  64
#define TI   32          // q-rows per CTA
#define NT   128         // threads (4 warps, 2x2 warp grid)
#define NJT  8           // 512/64 j-tiles
#define PB   72          // bf16 smem pitch (144B rows: ldmatrix conflict-free)
#define PEF  516         // f32 smem pitch for E

// smem byte offsets
#define OFF_KH 0                 // 64 x 72 bf16 = 9216 B
#define OFF_KL 9216
#define OFF_VH 18432
#define OFF_VL 27648
#define OFF_EH 36864             // 32 x 72 bf16 = 4608 B (also Q-hi staging)
#define OFF_EL 41472             // (also Q-lo staging)
#define OFF_EF 46080             // 32 x 516 f32 = 66048 B
#define OFF_MC 112128            // 512 f32
#define OFF_RS 114176            // 32 x 2 f32 partial row sums
#define OFF_RI 114432            // 32 f32 reciprocal row sums
#define SMEM_BYTES 114560

__device__ __forceinline__ uint32_t smem_u32(const void* p) {
    return (uint32_t)__cvta_generic_to_shared(p);
}
__device__ __forceinline__ void ldsm4(uint32_t* r, uint32_t a) {
    asm volatile("ldmatrix.sync.aligned.m8n8.x4.shared.b16 {%0,%1,%2,%3}, [%4];"
                 : "=r"(r[0]), "=r"(r[1]), "=r"(r[2]), "=r"(r[3]) : "r"(a));
}
__device__ __forceinline__ void ldsm4t(uint32_t* r, uint32_t a) {
    asm volatile("ldmatrix.sync.aligned.m8n8.x4.trans.shared.b16 {%0,%1,%2,%3}, [%4];"
                 : "=r"(r[0]), "=r"(r[1]), "=r"(r[2]), "=r"(r[3]) : "r"(a));
}
__device__ __forceinline__ void mma_bf16(float* c, const uint32_t* a, uint32_t b0, uint32_t b1) {
    asm volatile("mma.sync.aligned.m16n8k16.row.col.f32.bf16.bf16.f32 "
                 "{%0,%1,%2,%3}, {%4,%5,%6,%7}, {%8,%9}, {%0,%1,%2,%3};"
                 : "+f"(c[0]), "+f"(c[1]), "+f"(c[2]), "+f"(c[3])
                 : "r"(a[0]), "r"(a[1]), "r"(a[2]), "r"(a[3]), "r"(b0), "r"(b1));
}
// split two f32 into packed bf16 hi-pair and lo-pair
__device__ __forceinline__ void split2(float x0, float x1, uint32_t& h, uint32_t& l) {
    __nv_bfloat16 h0 = __float2bfloat16(x0);
    __nv_bfloat16 h1 = __float2bfloat16(x1);
    __nv_bfloat16 l0 = __float2bfloat16(x0 - __bfloat162float(h0));
    __nv_bfloat16 l1 = __float2bfloat16(x1 - __bfloat162float(h1));
    __nv_bfloat162 hp = __nv_bfloat162(h0, h1);
    __nv_bfloat162 lp = __nv_bfloat162(l0, l1);
    h = *reinterpret_cast<uint32_t*>(&hp);
    l = *reinterpret_cast<uint32_t*>(&lp);
}

__global__ void __launch_bounds__(NT)
attn_tc_kernel(const float* __restrict__ q,
               const float* __restrict__ k,
               const float* __restrict__ v,
               const float* __restrict__ mask,
               float* __restrict__ out_o,
               float* __restrict__ out_attn)
{
    extern __shared__ char smc[];
    __nv_bfloat16* Kh = (__nv_bfloat16*)(smc + OFF_KH);
    __nv_bfloat16* Kl = (__nv_bfloat16*)(smc + OFF_KL);
    __nv_bfloat16* Vh = (__nv_bfloat16*)(smc + OFF_VH);
    __nv_bfloat16* Vl = (__nv_bfloat16*)(smc + OFF_VL);
    __nv_bfloat16* Eh = (__nv_bfloat16*)(smc + OFF_EH);
    __nv_bfloat16* El = (__nv_bfloat16*)(smc + OFF_EL);
    float* Ef = (float*)(smc + OFF_EF);
    float* mc = (float*)(smc + OFF_MC);
    float (*rsp)[2] = (float (*)[2])(smc + OFF_RS);
    float* rinv = (float*)(smc + OFF_RI);

    const int bh  = blockIdx.y;
    const int i0  = blockIdx.x * TI;
    const int b   = bh >> 3;             // H = 8
    const int tid = threadIdx.x;
    const int L   = tid & 31;            // lane
    const int w   = tid >> 5;
    const int wi  = w >> 1;              // 0..1 -> 16-row half
    const int wj  = w & 1;               // 0..1 -> 32-col half
    const int g   = L >> 2;              // frag row group
    const int t   = L & 3;               // frag col pair

    const uint32_t khB = smem_u32(Kh);
    const uint32_t vhB = smem_u32(Vh);
    const uint32_t ehB = smem_u32(Eh);

    // column mask term: 0 or 1e9
    for (int j = tid; j < LEN; j += NT) {
        float mv = mask[b * LEN + j];
        mc[j] = (mv == -10000.0f) ? 1e9f : mv;
    }

    // ---- Q prologue: stage 32x64 hi/lo bf16 into Eh/El, ldmatrix into regs ----
    {
        const float* qb = q + ((size_t)bh * LEN + i0) * DIM;
        #pragma unroll
        for (int it = 0; it < 4; it++) {
            int lin4 = it * NT + tid;            // 0..511
            int row = lin4 >> 4;                 // 16 float4 per row
            int c4  = (lin4 & 15) * 4;
            float4 qv = *(const float4*)(qb + row * DIM + c4);
            uint32_t h01, l01, h23, l23;
            split2(qv.x, qv.y, h01, l01);
            split2(qv.z, qv.w, h23, l23);
            *(uint32_t*)&Eh[row * PB + c4]     = h01;
            *(uint32_t*)&Eh[row * PB + c4 + 2] = h23;
            *(uint32_t*)&El[row * PB + c4]     = l01;
            *(uint32_t*)&El[row * PB + c4 + 2] = l23;
        }
    }
    __syncthreads();

    uint32_t qa_h[4][4], qa_l[4][4];
    {
        int arow = wi * 16 + (L & 15);
        int acol = (L >> 4) * 8;
        #pragma unroll
        for (int ks = 0; ks < 4; ks++) {
            uint32_t a = ehB + (uint32_t)(arow * PB + ks * 16 + acol) * 2;
            ldsm4(qa_h[ks], a);
            ldsm4(qa_l[ks], a + (OFF_EL - OFF_EH));
        }
    }

    float oacc[4][4];
    #pragma unroll
    for (int n = 0; n < 4; n++)
        #pragma unroll
        for (int c = 0; c < 4; c++) oacc[n][c] = 0.0f;
    float rs0 = 0.0f, rs1 = 0.0f;

    const float* kb = k + (size_t)bh * LEN * DIM;
    const float* vb = v + (size_t)bh * LEN * DIM;

    // frag row/col helpers
    const int r0l = wi * 16 + g;          // local row of c0/c1
    const int r1l = r0l + 8;              // local row of c2/c3
    const bool rm0 = false, rm1 = false;  // placeholders (set below per CTA)
    (void)rm0; (void)rm1;

    // GEMM1 B (K, non-trans) address components
    const int b1row  = wj * 32 + ((L >> 4) & 1) * 8 + (L & 7);
    const int b1colh = ((L >> 3) & 1) * 8;
    // GEMM2 A (E) address components
    const int a2row  = wi * 16 + (L & 15);
    const int a2colh = (L >> 4) * 8;
    // GEMM2 B (V, trans) address components
    const int b2rowh = ((L >> 3) & 1) * 8 + (L & 7);
    const int b2col  = wj * 32 + (L >> 4) * 8;

    const bool rowM0 = (mc[i0 + r0l] != 0.0f);
    const bool rowM1 = (mc[i0 + r1l] != 0.0f);

    for (int jt = 0; jt < NJT; jt++) {
        const int j0 = jt * 64;
        __syncthreads();   // prior consumers of K/V/Eh/El done

        // ---- load + split K/V tile (64x64 f32 each) ----
        {
            const float* kt = kb + (size_t)j0 * DIM;
            const float* vt = vb + (size_t)j0 * DIM;
            #pragma unroll
            for (int it = 0; it < 8; it++) {
                int lin4 = it * NT + tid;        // 0..1023
                int row = lin4 >> 4;
                int c4  = (lin4 & 15) * 4;
                float4 kv = *(const float4*)(kt + row * DIM + c4);
                float4 vv = *(const float4*)(vt + row * DIM + c4);
                uint32_t h01, l01, h23, l23;
                split2(kv.x, kv.y, h01, l01); split2(kv.z, kv.w, h23, l23);
                *(uint32_t*)&Kh[row * PB + c4]     = h01;
                *(uint32_t*)&Kh[row * PB + c4 + 2] = h23;
                *(uint32_t*)&Kl[row * PB + c4]     = l01;
                *(uint32_t*)&Kl[row * PB + c4 + 2] = l23;
                split2(vv.x, vv.y, h01, l01); split2(vv.z, vv.w, h23, l23);
                *(uint32_t*)&Vh[row * PB + c4]     = h01;
                *(uint32_t*)&Vh[row * PB + c4 + 2] = h23;
                *(uint32_t*)&Vl[row * PB + c4]     = l01;
                *(uint32_t*)&Vl[row * PB + c4 + 2] = l23;
            }
        }
        __syncthreads();

        // ---- GEMM1: S(16x32 per warp) = Q.K^T via 3-pass bf16 split ----
        float sacc[4][4];
        #pragma unroll
        for (int n = 0; n < 4; n++)
            #pragma unroll
            for (int c = 0; c < 4; c++) sacc[n][c] = 0.0f;

        #pragma unroll
        for (int ks = 0; ks < 4; ks++) {
            #pragma unroll
            for (int p = 0; p < 2; p++) {
                uint32_t addr = khB + (uint32_t)((b1row + p * 16) * PB + ks * 16 + b1colh) * 2;
                uint32_t bh4[4], bl4[4];
                ldsm4(bh4, addr);
                ldsm4(bl4, addr + (OFF_KL - OFF_KH));
                mma_bf16(sacc[2 * p],     qa_h[ks], bh4[0], bh4[1]);
                mma_bf16(sacc[2 * p + 1], qa_h[ks], bh4[2], bh4[3]);
                mma_bf16(sacc[2 * p],     qa_h[ks], bl4[0], bl4[1]);
                mma_bf16(sacc[2 * p + 1], qa_h[ks], bl4[2], bl4[3]);
                mma_bf16(sacc[2 * p],     qa_l[ks], bh4[0], bh4[1]);
                mma_bf16(sacc[2 * p + 1], qa_l[ks], bh4[2], bh4[3]);
            }
        }

        // ---- epilogue: exp + mask, store Ef (f32) and Eh/El (bf16), rowsums ----
        #pragma unroll
        for (int nb = 0; nb < 4; nb++) {
            int lcol = wj * 32 + nb * 8 + 2 * t;   // local col in j-tile
            int jj = j0 + lcol;                    // global col
            float mj0 = mc[jj], mj1 = mc[jj + 1];
            float u0 = (mj0 == 0.0f) ? 1.0f : 0.0f;
            float u1 = (mj1 == 0.0f) ? 1.0f : 0.0f;
            float e00 = rowM0 ? u0 : __expf(fmaf(sacc[nb][0], 0.125f, -mj0));
            float e01 = rowM0 ? u1 : __expf(fmaf(sacc[nb][1], 0.125f, -mj1));
            float e10 = rowM1 ? u0 : __expf(fmaf(sacc[nb][2], 0.125f, -mj0));
            float e11 = rowM1 ? u1 : __expf(fmaf(sacc[nb][3], 0.125f, -mj1));
            rs0 += e00 + e01;
            rs1 += e10 + e11;
            float2 f0 = make_float2(e00, e01);
            float2 f1 = make_float2(e10, e11);
            *(float2*)&Ef[r0l * PEF + jj] = f0;
            *(float2*)&Ef[r1l * PEF + jj] = f1;
            uint32_t h2, l2;
            split2(e00, e01, h2, l2);
            *(uint32_t*)&Eh[r0l * PB + lcol] = h2;
            *(uint32_t*)&El[r0l * PB + lcol] = l2;
            split2(e10, e11, h2, l2);
            *(uint32_t*)&Eh[r1l * PB + lcol] = h2;
            *(uint32_t*)&El[r1l * PB + lcol] = l2;
        }
        __syncthreads();

        // ---- GEMM2: O(16x32 per warp) += E.V via 3-pass bf16 split ----
        #pragma unroll
        for (int ks = 0; ks < 4; ks++) {
            uint32_t aaddr = ehB + (uint32_t)(a2row * PB + ks * 16 + a2colh) * 2;
            uint32_t ah4[4], al4[4];
            ldsm4(ah4, aaddr);
            ldsm4(al4, aaddr + (OFF_EL - OFF_EH));
            #pragma unroll
            for (int p = 0; p < 2; p++) {
                uint32_t vaddr = vhB + (uint32_t)((ks * 16 + b2rowh) * PB + b2col + p * 16) * 2;
                uint32_t vh4[4], vl4[4];
                ldsm4t(vh4, vaddr);
                ldsm4t(vl4, vaddr + (OFF_VL - OFF_VH));
                mma_bf16(oacc[2 * p],     ah4, vh4[0], vh4[1]);
                mma_bf16(oacc[2 * p + 1], ah4, vh4[2], vh4[3]);
                mma_bf16(oacc[2 * p],     ah4, vl4[0], vl4[1]);
                mma_bf16(oacc[2 * p + 1], ah4, vl4[2], vl4[3]);
                mma_bf16(oacc[2 * p],     al4, vh4[0], vh4[1]);
                mma_bf16(oacc[2 * p + 1], al4, vh4[2], vh4[3]);
            }
        }
    }

    // ---- rowsum reduction across t-lanes (lanes 4g..4g+3) and wj warps ----
    rs0 += __shfl_xor_sync(0xffffffffu, rs0, 1);
    rs0 += __shfl_xor_sync(0xffffffffu, rs0, 2);
    rs1 += __shfl_xor_sync(0xffffffffu, rs1, 1);
    rs1 += __shfl_xor_sync(0xffffffffu, rs1, 2);
    if (t == 0) {
        rsp[r0l][wj] = rs0;
        rsp[r1l][wj] = rs1;
    }
    __syncthreads();
    if (tid < TI) rinv[tid] = 1.0f / (rsp[tid][0] + rsp[tid][1]);
    __syncthreads();

    // ---- write O ----
    if (out_o) {
        float* ob = out_o + ((size_t)bh * LEN + i0) * DIM;
        float inv0 = rinv[r0l];
        float inv1 = rinv[r1l];
        #pragma unroll
        for (int nb = 0; nb < 4; nb++) {
            int dcol = wj * 32 + nb * 8 + 2 * t;
            float2 o0 = make_float2(oacc[nb][0] * inv0, oacc[nb][1] * inv0);
            float2 o1 = make_float2(oacc[nb][2] * inv1, oacc[nb][3] * inv1);
            *(float2*)&ob[r0l * DIM + dcol] = o0;
            *(float2*)&ob[r1l * DIM + dcol] = o1;
        }
    }

    // ---- write attn = Ef * rinv ----
    if (out_attn) {
        float* ab = out_attn + ((size_t)bh * LEN + i0) * LEN;
        #pragma unroll 4
        for (int i4 = tid; i4 < TI * (LEN / 4); i4 += NT) {
            int row = i4 >> 7;              // 128 float4 per row
            int col = (i4 & 127) * 4;
            float inv = rinv[row];
            float4 e = *(const float4*)&Ef[row * PEF + col];
            e.x *= inv; e.y *= inv; e.z *= inv; e.w *= inv;
            *(float4*)&ab[(size_t)row * LEN + col] = e;
        }
    }
}

extern "C" void kernel_launch(void* const* d_in, const int* in_sizes, int n_in,
                              void* d_out, int out_size)
{
    const float* q    = (const float*)d_in[0];
    const float* k    = (const float*)d_in[1];
    const float* v    = (const float*)d_in[2];
    const float* mask = (const float*)d_in[3];

    const long long O_ELEMS = (long long)BH * LEN * DIM;   // 4194304
    const long long A_ELEMS = (long long)BH * LEN * LEN;   // 33554432

    float* out = (float*)d_out;
    float* o_ptr = nullptr;
    float* a_ptr = nullptr;
    if ((long long)out_size >= O_ELEMS + A_ELEMS) {
        o_ptr = out;
        a_ptr = out + O_ELEMS;
    } else if ((long long)out_size == A_ELEMS) {
        a_ptr = out;
    } else {
        o_ptr = out;
    }

    cudaFuncSetAttribute(attn_tc_kernel,
                         cudaFuncAttributeMaxDynamicSharedMemorySize, SMEM_BYTES);

    dim3 grid(LEN / TI, BH);   // (16, 128) = 2048 CTAs
    attn_tc_kernel<<<grid, NT, SMEM_BYTES>>>(q, k, v, mask, o_ptr, a_ptr);
}

// round 4
// speedup vs baseline: 1.8414x; 1.1328x over previous
#include <cuda_runtime.h>
#include <cuda_bf16.h>
#include <cstdint>
#include <cstddef>

// Problem constants: B=16, H=8, L=512, D=64
#define BH   128
#define LEN  512
#define DIM  64
#define TI   32          // q-rows per CTA
#define NT   256         // threads (8 warps, 2x4 warp grid)
#define NJT  8           // 512/64 j-tiles
#define PB   72          // bf16 smem pitch
#define PEF  516         // f32 smem pitch for E

// smem byte offsets
#define OFF_KH 0                 // 64 x 72 bf16 = 9216 B
#define OFF_KL 9216
#define OFF_VH 18432
#define OFF_VL 27648
#define OFF_EH 36864             // 32 x 72 bf16 = 4608 B (also Q-hi staging)
#define OFF_EL 41472
#define OFF_EF 46080             // 32 x 516 f32 = 66048 B
#define OFF_MC 112128            // 512 f32
#define OFF_RS 114176            // 32 x 4 f32 partial row sums
#define OFF_RI 114688            // 32 f32 reciprocal row sums
#define SMEM_BYTES 114816

__device__ __forceinline__ uint32_t smem_u32(const void* p) {
    return (uint32_t)__cvta_generic_to_shared(p);
}
__device__ __forceinline__ void ldsm4(uint32_t* r, uint32_t a) {
    asm volatile("ldmatrix.sync.aligned.m8n8.x4.shared.b16 {%0,%1,%2,%3}, [%4];"
                 : "=r"(r[0]), "=r"(r[1]), "=r"(r[2]), "=r"(r[3]) : "r"(a));
}
__device__ __forceinline__ void ldsm4t(uint32_t* r, uint32_t a) {
    asm volatile("ldmatrix.sync.aligned.m8n8.x4.trans.shared.b16 {%0,%1,%2,%3}, [%4];"
                 : "=r"(r[0]), "=r"(r[1]), "=r"(r[2]), "=r"(r[3]) : "r"(a));
}
__device__ __forceinline__ void mma_bf16(float* c, const uint32_t* a, uint32_t b0, uint32_t b1) {
    asm volatile("mma.sync.aligned.m16n8k16.row.col.f32.bf16.bf16.f32 "
                 "{%0,%1,%2,%3}, {%4,%5,%6,%7}, {%8,%9}, {%0,%1,%2,%3};"
                 : "+f"(c[0]), "+f"(c[1]), "+f"(c[2]), "+f"(c[3])
                 : "r"(a[0]), "r"(a[1]), "r"(a[2]), "r"(a[3]), "r"(b0), "r"(b1));
}
__device__ __forceinline__ void split2(float x0, float x1, uint32_t& h, uint32_t& l) {
    __nv_bfloat16 h0 = __float2bfloat16(x0);
    __nv_bfloat16 h1 = __float2bfloat16(x1);
    __nv_bfloat16 l0 = __float2bfloat16(x0 - __bfloat162float(h0));
    __nv_bfloat16 l1 = __float2bfloat16(x1 - __bfloat162float(h1));
    __nv_bfloat162 hp = __nv_bfloat162(h0, h1);
    __nv_bfloat162 lp = __nv_bfloat162(l0, l1);
    h = *reinterpret_cast<uint32_t*>(&hp);
    l = *reinterpret_cast<uint32_t*>(&lp);
}

__global__ void __launch_bounds__(NT, 2)
attn_tc_kernel(const float* __restrict__ q,
               const float* __restrict__ k,
               const float* __restrict__ v,
               const float* __restrict__ mask,
               float* __restrict__ out_o,
               float* __restrict__ out_attn)
{
    extern __shared__ char smc[];
    __nv_bfloat16* Kh = (__nv_bfloat16*)(smc + OFF_KH);
    __nv_bfloat16* Kl = (__nv_bfloat16*)(smc + OFF_KL);
    __nv_bfloat16* Vh = (__nv_bfloat16*)(smc + OFF_VH);
    __nv_bfloat16* Vl = (__nv_bfloat16*)(smc + OFF_VL);
    __nv_bfloat16* Eh = (__nv_bfloat16*)(smc + OFF_EH);
    __nv_bfloat16* El = (__nv_bfloat16*)(smc + OFF_EL);
    float* Ef = (float*)(smc + OFF_EF);
    float* mc = (float*)(smc + OFF_MC);
    float (*rsp)[4] = (float (*)[4])(smc + OFF_RS);
    float* rinv = (float*)(smc + OFF_RI);

    const int bh  = blockIdx.y;
    const int i0  = blockIdx.x * TI;
    const int b   = bh >> 3;             // H = 8
    const int tid = threadIdx.x;
    const int L   = tid & 31;            // lane
    const int w   = tid >> 5;            // warp 0..7
    const int wi  = w & 1;               // 16-row half
    const int wj  = w >> 1;              // 0..3 -> 16-col group
    const int g   = L >> 2;              // frag row group
    const int t   = L & 3;               // frag col pair

    const uint32_t khB = smem_u32(Kh);
    const uint32_t vhB = smem_u32(Vh);
    const uint32_t ehB = smem_u32(Eh);

    // column mask term: 0 or 1e9
    for (int j = tid; j < LEN; j += NT) {
        float mv = mask[b * LEN + j];
        mc[j] = (mv == -10000.0f) ? 1e9f : mv;
    }

    // ---- Q prologue: stage 32x64 hi/lo bf16 into Eh/El, ldmatrix into regs ----
    {
        const float* qb = q + ((size_t)bh * LEN + i0) * DIM;
        #pragma unroll
        for (int it = 0; it < 2; it++) {
            int lin4 = it * NT + tid;            // 0..511
            int row = lin4 >> 4;                 // 16 float4 per row
            int c4  = (lin4 & 15) * 4;
            float4 qv = *(const float4*)(qb + row * DIM + c4);
            uint32_t h01, l01, h23, l23;
            split2(qv.x, qv.y, h01, l01);
            split2(qv.z, qv.w, h23, l23);
            *(uint32_t*)&Eh[row * PB + c4]     = h01;
            *(uint32_t*)&Eh[row * PB + c4 + 2] = h23;
            *(uint32_t*)&El[row * PB + c4]     = l01;
            *(uint32_t*)&El[row * PB + c4 + 2] = l23;
        }
    }
    __syncthreads();

    uint32_t qa_h[4][4], qa_l[4][4];
    {
        int arow = wi * 16 + (L & 15);
        int acol = (L >> 4) * 8;
        #pragma unroll
        for (int ks = 0; ks < 4; ks++) {
            uint32_t a = ehB + (uint32_t)(arow * PB + ks * 16 + acol) * 2;
            ldsm4(qa_h[ks], a);
            ldsm4(qa_l[ks], a + (OFF_EL - OFF_EH));
        }
    }

    float oacc[2][4];
    #pragma unroll
    for (int n = 0; n < 2; n++)
        #pragma unroll
        for (int c = 0; c < 4; c++) oacc[n][c] = 0.0f;
    float rs0 = 0.0f, rs1 = 0.0f;

    const float* kb = k + (size_t)bh * LEN * DIM;
    const float* vb = v + (size_t)bh * LEN * DIM;

    const int r0l = wi * 16 + g;          // local row of c0/c1
    const int r1l = r0l + 8;              // local row of c2/c3

    // GEMM1 B (K, non-trans): 16 j-rows x 16 k-cols per ks
    const int b1row  = wj * 16 + ((L >> 4) & 1) * 8 + (L & 7);
    const int b1colh = ((L >> 3) & 1) * 8;
    // GEMM2 A (E)
    const int a2row  = wi * 16 + (L & 15);
    const int a2colh = (L >> 4) * 8;
    // GEMM2 B (V, trans): 16 k-rows x 16 d-cols per ks
    const int b2rowh = ((L >> 3) & 1) * 8 + (L & 7);
    const int b2col  = wj * 16 + (L >> 4) * 8;

    const bool rowM0 = (mc[i0 + r0l] != 0.0f);
    const bool rowM1 = (mc[i0 + r1l] != 0.0f);

    for (int jt = 0; jt < NJT; jt++) {
        const int j0 = jt * 64;
        __syncthreads();   // prior consumers of K/V/Eh/El done

        // ---- load + split K/V tile (64x64 f32 each) ----
        {
            const float* kt = kb + (size_t)j0 * DIM;
            const float* vt = vb + (size_t)j0 * DIM;
            #pragma unroll
            for (int it = 0; it < 4; it++) {
                int lin4 = it * NT + tid;        // 0..1023
                int row = lin4 >> 4;
                int c4  = (lin4 & 15) * 4;
                float4 kv = *(const float4*)(kt + row * DIM + c4);
                float4 vv = *(const float4*)(vt + row * DIM + c4);
                uint32_t h01, l01, h23, l23;
                split2(kv.x, kv.y, h01, l01); split2(kv.z, kv.w, h23, l23);
                *(uint32_t*)&Kh[row * PB + c4]     = h01;
                *(uint32_t*)&Kh[row * PB + c4 + 2] = h23;
                *(uint32_t*)&Kl[row * PB + c4]     = l01;
                *(uint32_t*)&Kl[row * PB + c4 + 2] = l23;
                split2(vv.x, vv.y, h01, l01); split2(vv.z, vv.w, h23, l23);
                *(uint32_t*)&Vh[row * PB + c4]     = h01;
                *(uint32_t*)&Vh[row * PB + c4 + 2] = h23;
                *(uint32_t*)&Vl[row * PB + c4]     = l01;
                *(uint32_t*)&Vl[row * PB + c4 + 2] = l23;
            }
        }
        __syncthreads();

        // ---- GEMM1: S(16x16 per warp) = Q.K^T via 3-pass bf16 split ----
        float sacc[2][4];
        #pragma unroll
        for (int n = 0; n < 2; n++)
            #pragma unroll
            for (int c = 0; c < 4; c++) sacc[n][c] = 0.0f;

        #pragma unroll
        for (int ks = 0; ks < 4; ks++) {
            uint32_t addr = khB + (uint32_t)(b1row * PB + ks * 16 + b1colh) * 2;
            uint32_t bh4[4], bl4[4];
            ldsm4(bh4, addr);
            ldsm4(bl4, addr + (OFF_KL - OFF_KH));
            mma_bf16(sacc[0], qa_h[ks], bh4[0], bh4[1]);
            mma_bf16(sacc[1], qa_h[ks], bh4[2], bh4[3]);
            mma_bf16(sacc[0], qa_h[ks], bl4[0], bl4[1]);
            mma_bf16(sacc[1], qa_h[ks], bl4[2], bl4[3]);
            mma_bf16(sacc[0], qa_l[ks], bh4[0], bh4[1]);
            mma_bf16(sacc[1], qa_l[ks], bh4[2], bh4[3]);
        }

        // ---- epilogue: exp + mask, store Ef (f32) and Eh/El (bf16), rowsums ----
        #pragma unroll
        for (int nb = 0; nb < 2; nb++) {
            int lcol = wj * 16 + nb * 8 + 2 * t;   // local col in j-tile
            int jj = j0 + lcol;                    // global col
            float mj0 = mc[jj], mj1 = mc[jj + 1];
            float u0 = (mj0 == 0.0f) ? 1.0f : 0.0f;
            float u1 = (mj1 == 0.0f) ? 1.0f : 0.0f;
            float e00 = rowM0 ? u0 : __expf(fmaf(sacc[nb][0], 0.125f, -mj0));
            float e01 = rowM0 ? u1 : __expf(fmaf(sacc[nb][1], 0.125f, -mj1));
            float e10 = rowM1 ? u0 : __expf(fmaf(sacc[nb][2], 0.125f, -mj0));
            float e11 = rowM1 ? u1 : __expf(fmaf(sacc[nb][3], 0.125f, -mj1));
            rs0 += e00 + e01;
            rs1 += e10 + e11;
            *(float2*)&Ef[r0l * PEF + jj] = make_float2(e00, e01);
            *(float2*)&Ef[r1l * PEF + jj] = make_float2(e10, e11);
            uint32_t h2, l2;
            split2(e00, e01, h2, l2);
            *(uint32_t*)&Eh[r0l * PB + lcol] = h2;
            *(uint32_t*)&El[r0l * PB + lcol] = l2;
            split2(e10, e11, h2, l2);
            *(uint32_t*)&Eh[r1l * PB + lcol] = h2;
            *(uint32_t*)&El[r1l * PB + lcol] = l2;
        }
        __syncthreads();

        // ---- GEMM2: O(16x16 per warp) += E.V via 3-pass bf16 split ----
        #pragma unroll
        for (int ks = 0; ks < 4; ks++) {
            uint32_t aaddr = ehB + (uint32_t)(a2row * PB + ks * 16 + a2colh) * 2;
            uint32_t ah4[4], al4[4];
            ldsm4(ah4, aaddr);
            ldsm4(al4, aaddr + (OFF_EL - OFF_EH));
            uint32_t vaddr = vhB + (uint32_t)((ks * 16 + b2rowh) * PB + b2col) * 2;
            uint32_t vh4[4], vl4[4];
            ldsm4t(vh4, vaddr);
            ldsm4t(vl4, vaddr + (OFF_VL - OFF_VH));
            mma_bf16(oacc[0], ah4, vh4[0], vh4[1]);
            mma_bf16(oacc[1], ah4, vh4[2], vh4[3]);
            mma_bf16(oacc[0], ah4, vl4[0], vl4[1]);
            mma_bf16(oacc[1], ah4, vl4[2], vl4[3]);
            mma_bf16(oacc[0], al4, vh4[0], vh4[1]);
            mma_bf16(oacc[1], al4, vh4[2], vh4[3]);
        }
    }

    // ---- rowsum reduction across t-lanes then across the 4 wj warps ----
    rs0 += __shfl_xor_sync(0xffffffffu, rs0, 1);
    rs0 += __shfl_xor_sync(0xffffffffu, rs0, 2);
    rs1 += __shfl_xor_sync(0xffffffffu, rs1, 1);
    rs1 += __shfl_xor_sync(0xffffffffu, rs1, 2);
    if (t == 0) {
        rsp[r0l][wj] = rs0;
        rsp[r1l][wj] = rs1;
    }
    __syncthreads();
    if (tid < TI)
        rinv[tid] = 1.0f / (rsp[tid][0] + rsp[tid][1] + rsp[tid][2] + rsp[tid][3]);
    __syncthreads();

    // ---- write O ----
    if (out_o) {
        float* ob = out_o + ((size_t)bh * LEN + i0) * DIM;
        float inv0 = rinv[r0l];
        float inv1 = rinv[r1l];
        #pragma unroll
        for (int nb = 0; nb < 2; nb++) {
            int dcol = wj * 16 + nb * 8 + 2 * t;
            *(float2*)&ob[r0l * DIM + dcol] = make_float2(oacc[nb][0] * inv0, oacc[nb][1] * inv0);
            *(float2*)&ob[r1l * DIM + dcol] = make_float2(oacc[nb][2] * inv1, oacc[nb][3] * inv1);
        }
    }

    // ---- write attn = Ef * rinv ----
    if (out_attn) {
        float* ab = out_attn + ((size_t)bh * LEN + i0) * LEN;
        #pragma unroll 4
        for (int i4 = tid; i4 < TI * (LEN / 4); i4 += NT) {
            int row = i4 >> 7;              // 128 float4 per row
            int col = (i4 & 127) * 4;
            float inv = rinv[row];
            float4 e = *(const float4*)&Ef[row * PEF + col];
            e.x *= inv; e.y *= inv; e.z *= inv; e.w *= inv;
            *(float4*)&ab[(size_t)row * LEN + col] = e;
        }
    }
}

extern "C" void kernel_launch(void* const* d_in, const int* in_sizes, int n_in,
                              void* d_out, int out_size)
{
    const float* q    = (const float*)d_in[0];
    const float* k    = (const float*)d_in[1];
    const float* v    = (const float*)d_in[2];
    const float* mask = (const float*)d_in[3];

    const long long O_ELEMS = (long long)BH * LEN * DIM;   // 4194304
    const long long A_ELEMS = (long long)BH * LEN * LEN;   // 33554432

    float* out = (float*)d_out;
    float* o_ptr = nullptr;
    float* a_ptr = nullptr;
    if ((long long)out_size >= O_ELEMS + A_ELEMS) {
        o_ptr = out;
        a_ptr = out + O_ELEMS;
    } else if ((long long)out_size == A_ELEMS) {
        a_ptr = out;
    } else {
        o_ptr = out;
    }

    cudaFuncSetAttribute(attn_tc_kernel,
                         cudaFuncAttributeMaxDynamicSharedMemorySize, SMEM_BYTES);

    dim3 grid(LEN / TI, BH);   // (16, 128) = 2048 CTAs
    attn_tc_kernel<<<grid, NT, SMEM_BYTES>>>(q, k, v, mask, o_ptr, a_ptr);
}